// round 17
// baseline (speedup 1.0000x reference)
#include <cuda_runtime.h>
#include <cuda_bf16.h>
#include <cstdint>

// Problem constants
#define Bn    8
#define NN    2048
#define FINx  512
#define FOUTx 256
#define MTOT  (Bn*NN)          // 16384
#define ALPHAc 0.2f
#define NEGc  (-9e15f)
#define EXPSHIFT 40.0f

// ---------------- scratch (device globals: allocation-free) ----------------
__device__ __nv_bfloat16 g_hh1hi[(size_t)MTOT*512];  // [h | h1] hi (ld 512)
__device__ __nv_bfloat16 g_hh1lo[(size_t)MTOT*512];
__device__ float g_h2[MTOT*FOUTx];            // fa@W2
__device__ float g_Ax[MTOT];
__device__ float g_Ay[MTOT];
__device__ float g_e1[MTOT*8];
__device__ float g_e2[MTOT*8];
__device__ float g_rowpart[(size_t)MTOT*32];  // scores row partial sums
__device__ float g_invsum[MTOT];              // 1/rowsum
__device__ __nv_bfloat16 g_Shi[(size_t)Bn*NN*NN];   // unnorm probs hi
__device__ __nv_bfloat16 g_Slo[(size_t)Bn*NN*NN];   // unnorm probs lo
__device__ __nv_bfloat16 g_Fhi[(size_t)Bn*FINx*NN]; // featT hi
__device__ __nv_bfloat16 g_Flo[(size_t)Bn*FINx*NN]; // featT lo
__device__ __nv_bfloat16 g_fRhi[(size_t)MTOT*FINx]; // feat row-major hi
__device__ __nv_bfloat16 g_fRlo[(size_t)MTOT*FINx];
__device__ __nv_bfloat16 g_fahi[(size_t)MTOT*FINx]; // fa hi (normalized)
__device__ __nv_bfloat16 g_falo[(size_t)MTOT*FINx];
__device__ __nv_bfloat16 g_ghi[MTOT*FOUTx];   // g hi
__device__ __nv_bfloat16 g_glo[MTOT*FOUTx];
__device__ __nv_bfloat16 g_WW1th[512*FINx];   // [W^T ; W1^T] hi
__device__ __nv_bfloat16 g_WW1tl[512*FINx];
__device__ __nv_bfloat16 g_W2th[FOUTx*FINx];
__device__ __nv_bfloat16 g_W2tl[FOUTx*FINx];
__device__ __nv_bfloat16 g_a12th[FOUTx*FOUTx];
__device__ __nv_bfloat16 g_a12tl[FOUTx*FOUTx];

// ---------------- mma.sync / cp.async helpers (sm_80+) ----------------------
__device__ __forceinline__ uint32_t smem_u32(const void* p) {
    return (uint32_t)__cvta_generic_to_shared(p);
}
__device__ __forceinline__ void cp16(uint32_t s, const void* g) {
    asm volatile("cp.async.cg.shared.global [%0], [%1], 16;" :: "r"(s), "l"(g));
}
__device__ __forceinline__ void ldmx4(uint32_t* d, uint32_t a) {
    asm volatile("ldmatrix.sync.aligned.m8n8.x4.shared.b16 {%0,%1,%2,%3}, [%4];"
                 : "=r"(d[0]), "=r"(d[1]), "=r"(d[2]), "=r"(d[3]) : "r"(a));
}
__device__ __forceinline__ void mma_bf16(float* c, const uint32_t* a,
                                         uint32_t b0, uint32_t b1) {
    asm volatile("mma.sync.aligned.m16n8k16.row.col.f32.bf16.bf16.f32 "
                 "{%0,%1,%2,%3}, {%4,%5,%6,%7}, {%8,%9}, {%0,%1,%2,%3};"
                 : "+f"(c[0]), "+f"(c[1]), "+f"(c[2]), "+f"(c[3])
                 : "r"(a[0]), "r"(a[1]), "r"(a[2]), "r"(a[3]), "r"(b0), "r"(b1));
}
__device__ __forceinline__ float lrelu(float v) {
    return (v > 0.f) ? v : ALPHAc * v;
}
__device__ __forceinline__ float fast_exp(float x) {
    float t = x * 1.44269504088896f;
    t = fmaxf(t, -126.0f);
    const float n = rintf(t);
    const float f = t - n;
    float p = 1.5403530394e-4f;
    p = fmaf(p, f, 1.3333558146e-3f);
    p = fmaf(p, f, 9.6181291076e-3f);
    p = fmaf(p, f, 5.5504108664e-2f);
    p = fmaf(p, f, 2.4022650696e-1f);
    p = fmaf(p, f, 6.9314718056e-1f);
    p = fmaf(p, f, 1.0f);
    const int e = (int)n;
    return __int_as_float((e + 127) << 23) * p;
}
__device__ __forceinline__ void split_bf16(float v, __nv_bfloat16& h, __nv_bfloat16& l) {
    h = __float2bfloat16_rn(v);
    l = __float2bfloat16_rn(v - __bfloat162float(h));
}

// ---------------- HMMA GEMM: C = A @ B^T (bf16 3-pass split) ---------------
// EPI==0: fp32. EPI==3: hi/lo only.
// EPI==5: scores: exp(lrelu(acc+Ay+Ax)-40) masked->0, hi/lo store + row partial sums.
// EPI==4: agg: scale by invsum[row] (passed via Ax), hi/lo store.
#define AGG_ROWB  80
#define AGG_ARR   10240
#define AGG_BUF   (4*AGG_ARR)
#define AGG_SMEM  (2*AGG_BUF)

template<int EPI>
__global__ void __launch_bounds__(256)
mma_gemm_k(const __nv_bfloat16* __restrict__ Ah, const __nv_bfloat16* __restrict__ Al,
           const __nv_bfloat16* __restrict__ Bh, const __nv_bfloat16* __restrict__ Bl,
           float* __restrict__ C, int K, int lda, int ldb, int MA, int NB, int ldc,
           const float* __restrict__ Ax, const float* __restrict__ Ay,
           const int* __restrict__ adj, float* __restrict__ rowpart,
           __nv_bfloat16* __restrict__ Chi, __nv_bfloat16* __restrict__ Clo)
{
    extern __shared__ char smem[];
    const uint32_t sbase = smem_u32(smem);
    const int tid  = threadIdx.x;
    const int wid  = tid >> 5;
    const int lane = tid & 31;
    const int b  = blockIdx.z;
    const int m0 = blockIdx.y * 128;
    const int n0 = blockIdx.x * 128;

    const int r   = tid >> 2;
    const int seg = tid & 3;
    const __nv_bfloat16* gAh = Ah + ((size_t)b * MA + m0 + r) * lda + seg * 8;
    const __nv_bfloat16* gAl = Al + ((size_t)b * MA + m0 + r) * lda + seg * 8;
    const __nv_bfloat16* gBh = Bh + ((size_t)b * NB + n0 + r) * ldb + seg * 8;
    const __nv_bfloat16* gBl = Bl + ((size_t)b * NB + n0 + r) * ldb + seg * 8;
    const uint32_t sA = r * AGG_ROWB + seg * 16;
    const size_t gstepA = (size_t)64 * lda;
    const size_t gstepB = (size_t)64 * ldb;

    #define AGG_ISSUE(bufi, kc) do {                                           \
        const int kofs = (kc) * 32;                                            \
        uint32_t s0 = sbase + (bufi) * AGG_BUF + sA;                            \
        cp16(s0 + 0*AGG_ARR,               gAh + kofs);                         \
        cp16(s0 + 1*AGG_ARR,               gAl + kofs);                         \
        cp16(s0 + 2*AGG_ARR,               gBh + kofs);                         \
        cp16(s0 + 3*AGG_ARR,               gBl + kofs);                         \
        uint32_t s1 = s0 + 64 * AGG_ROWB;                                       \
        cp16(s1 + 0*AGG_ARR,               gAh + gstepA + kofs);                \
        cp16(s1 + 1*AGG_ARR,               gAl + gstepA + kofs);                \
        cp16(s1 + 2*AGG_ARR,               gBh + gstepB + kofs);                \
        cp16(s1 + 3*AGG_ARR,               gBl + gstepB + kofs);                \
        asm volatile("cp.async.commit_group;" ::: "memory");                    \
    } while (0)

    const int wm = wid & 3;
    const int wn = wid >> 2;

    float acc[2][8][4];
    #pragma unroll
    for (int mi = 0; mi < 2; mi++)
        #pragma unroll
        for (int nj = 0; nj < 8; nj++)
            #pragma unroll
            for (int q = 0; q < 4; q++) acc[mi][nj][q] = 0.f;

    const int NC = K / 32;
    AGG_ISSUE(0, 0);
    int buf = 0;
    for (int kc = 0; kc < NC; kc++) {
        if (kc + 1 < NC) {
            AGG_ISSUE(buf ^ 1, kc + 1);
            asm volatile("cp.async.wait_group 1;" ::: "memory");
        } else {
            asm volatile("cp.async.wait_group 0;" ::: "memory");
        }
        __syncthreads();

        const uint32_t base = sbase + buf * AGG_BUF;
        #pragma unroll
        for (int kq = 0; kq < 2; kq++) {
            const uint32_t aaddr = base
                + (uint32_t)((wm * 32 + (lane & 15)) * AGG_ROWB)
                + (uint32_t)((kq * 16 + (lane >> 4) * 8) * 2);
            uint32_t ah0[4], ah1[4], al0[4], al1[4];
            ldmx4(ah0, aaddr);
            ldmx4(ah1, aaddr + 16 * AGG_ROWB);
            ldmx4(al0, aaddr + 1*AGG_ARR);
            ldmx4(al1, aaddr + 1*AGG_ARR + 16 * AGG_ROWB);

            #pragma unroll
            for (int np = 0; np < 4; np++) {
                const uint32_t baddr = base + 2*AGG_ARR
                    + (uint32_t)((wn * 64 + np * 16 + (lane & 7) + ((lane >> 4) << 3)) * AGG_ROWB)
                    + (uint32_t)((kq * 16 + ((lane >> 3) & 1) * 8) * 2);
                uint32_t bh[4], bl[4];
                ldmx4(bh, baddr);
                ldmx4(bl, baddr + 1*AGG_ARR);
                const int j0 = np * 2, j1 = np * 2 + 1;
                mma_bf16(acc[0][j0], ah0, bh[0], bh[1]);
                mma_bf16(acc[0][j1], ah0, bh[2], bh[3]);
                mma_bf16(acc[1][j0], ah1, bh[0], bh[1]);
                mma_bf16(acc[1][j1], ah1, bh[2], bh[3]);
                mma_bf16(acc[0][j0], ah0, bl[0], bl[1]);
                mma_bf16(acc[0][j1], ah0, bl[2], bl[3]);
                mma_bf16(acc[1][j0], ah1, bl[0], bl[1]);
                mma_bf16(acc[1][j1], ah1, bl[2], bl[3]);
                mma_bf16(acc[0][j0], al0, bh[0], bh[1]);
                mma_bf16(acc[0][j1], al0, bh[2], bh[3]);
                mma_bf16(acc[1][j0], al1, bh[0], bh[1]);
                mma_bf16(acc[1][j1], al1, bh[2], bh[3]);
            }
        }
        __syncthreads();
        buf ^= 1;
    }
    #undef AGG_ISSUE

    // epilogue
    const int mbase = m0 + wm * 32;
    const int nbase = n0 + wn * 64;
    #pragma unroll
    for (int mi = 0; mi < 2; mi++) {
        const int mrow = mbase + mi * 16 + (lane >> 2);
        float rs0 = 0.f, rs1 = 0.f;
        float s0 = 1.f, s1 = 1.f;
        if (EPI == 4) {
            // Ax carries invsum (already the reciprocal) — multiply directly.
            s0 = Ax[b * NN + mrow];
            s1 = Ax[b * NN + mrow + 8];
        }
        #pragma unroll
        for (int nj = 0; nj < 8; nj++) {
            const int nc = nbase + nj * 8 + (lane & 3) * 2;
            const size_t i0 = ((size_t)b * MA + mrow) * ldc + nc;
            if (EPI == 0) {
                float* d0 = C + i0;
                *(float2*)d0              = make_float2(acc[mi][nj][0], acc[mi][nj][1]);
                *(float2*)(d0 + 8 * ldc)  = make_float2(acc[mi][nj][2], acc[mi][nj][3]);
            } else if (EPI == 3 || EPI == 4) {
                const float2 v0 = make_float2(acc[mi][nj][0] * s0, acc[mi][nj][1] * s0);
                const float2 v1 = make_float2(acc[mi][nj][2] * s1, acc[mi][nj][3] * s1);
                __nv_bfloat162 H0, L0, H1, L1;
                split_bf16(v0.x, H0.x, L0.x); split_bf16(v0.y, H0.y, L0.y);
                split_bf16(v1.x, H1.x, L1.x); split_bf16(v1.y, H1.y, L1.y);
                *(__nv_bfloat162*)(Chi + i0)            = H0;
                *(__nv_bfloat162*)(Clo + i0)            = L0;
                *(__nv_bfloat162*)(Chi + i0 + 8 * ldc)  = H1;
                *(__nv_bfloat162*)(Clo + i0 + 8 * ldc)  = L1;
            } else { // EPI == 5: scores -> unnormalized probs
                const float2 axv = *(const float2*)(Ax + b * NN + nc);
                const float ay0 = Ay[b * NN + mrow];
                const float ay1 = Ay[b * NN + mrow + 8];
                float2 v0 = make_float2(lrelu(acc[mi][nj][0] + ay0 + axv.x),
                                        lrelu(acc[mi][nj][1] + ay0 + axv.y));
                float2 v1 = make_float2(lrelu(acc[mi][nj][2] + ay1 + axv.x),
                                        lrelu(acc[mi][nj][3] + ay1 + axv.y));
                const int* adp = adj + ((size_t)b * NN + mrow) * NN + nc;
                int2 a0v = *(const int2*)adp;
                int2 a1v = *(const int2*)(adp + 8 * NN);
                v0.x = (a0v.x > 0) ? fast_exp(v0.x - EXPSHIFT) : 0.f;
                v0.y = (a0v.y > 0) ? fast_exp(v0.y - EXPSHIFT) : 0.f;
                v1.x = (a1v.x > 0) ? fast_exp(v1.x - EXPSHIFT) : 0.f;
                v1.y = (a1v.y > 0) ? fast_exp(v1.y - EXPSHIFT) : 0.f;
                rs0 += v0.x + v0.y;
                rs1 += v1.x + v1.y;
                __nv_bfloat162 H0, L0, H1, L1;
                split_bf16(v0.x, H0.x, L0.x); split_bf16(v0.y, H0.y, L0.y);
                split_bf16(v1.x, H1.x, L1.x); split_bf16(v1.y, H1.y, L1.y);
                *(__nv_bfloat162*)(Chi + i0)            = H0;
                *(__nv_bfloat162*)(Clo + i0)            = L0;
                *(__nv_bfloat162*)(Chi + i0 + 8 * ldc)  = H1;
                *(__nv_bfloat162*)(Clo + i0 + 8 * ldc)  = L1;
            }
        }
        if (EPI == 5) {
            // quad-reduce (lanes with same lane>>2 hold the same rows)
            rs0 += __shfl_xor_sync(0xffffffffu, rs0, 1);
            rs0 += __shfl_xor_sync(0xffffffffu, rs0, 2);
            rs1 += __shfl_xor_sync(0xffffffffu, rs1, 1);
            rs1 += __shfl_xor_sync(0xffffffffu, rs1, 2);
            if ((lane & 3) == 0) {
                const int slot = blockIdx.x * 2 + wn;   // 0..31
                rowpart[((size_t)(b * NN + mrow))     * 32 + slot] = rs0;
                rowpart[((size_t)(b * NN + mrow + 8)) * 32 + slot] = rs1;
            }
        }
    }
}

// --------- invsum[row] = 1 / sum(rowpart[row][0..31]) ------------------------
__global__ void rowsum_inv_k(const float* __restrict__ part, float* __restrict__ inv)
{
    const int row = (blockIdx.x * blockDim.x + threadIdx.x) >> 5;
    const int ln = threadIdx.x & 31;
    if (row >= MTOT) return;
    float v = part[(size_t)row * 32 + ln];
    #pragma unroll
    for (int o = 16; o; o >>= 1) v += __shfl_xor_sync(0xffffffffu, v, o);
    if (ln == 0) inv[row] = 1.0f / v;
}

// --------- generic transpose + split: dst[c][r] = split(src[r][c]) ----------
__global__ void tsplit_k(const float* __restrict__ src,
                         __nv_bfloat16* __restrict__ hi,
                         __nv_bfloat16* __restrict__ lo, int R, int C)
{
    __shared__ float t[32][33];
    const int r0 = blockIdx.y * 32;
    const int c0 = blockIdx.x * 32;
    const int tx = threadIdx.x, ty = threadIdx.y;   // (32, 8)
    #pragma unroll
    for (int i = 0; i < 4; i++)
        t[ty + 8*i][tx] = src[(size_t)(r0 + ty + 8*i) * C + c0 + tx];
    __syncthreads();
    #pragma unroll
    for (int i = 0; i < 4; i++) {
        const float v = t[tx][ty + 8*i];
        __nv_bfloat16 h, l;
        split_bf16(v, h, l);
        const size_t idx = (size_t)(c0 + ty + 8*i) * R + r0 + tx;
        hi[idx] = h;
        lo[idx] = l;
    }
}

// --------- batched transpose + split; also emits row-major split ------------
__global__ void transpose_split_k(const float* __restrict__ feat,
                                  __nv_bfloat16* __restrict__ Fhi,
                                  __nv_bfloat16* __restrict__ Flo,
                                  __nv_bfloat16* __restrict__ fRhi,
                                  __nv_bfloat16* __restrict__ fRlo)
{
    __shared__ float t[32][33];
    const int b  = blockIdx.z;
    const int n0 = blockIdx.x * 32;
    const int f0 = blockIdx.y * 32;
    const int tx = threadIdx.x, ty = threadIdx.y;   // (32, 8)

    #pragma unroll
    for (int i = 0; i < 4; i++) {
        const float v = feat[((size_t)b * NN + n0 + ty + 8*i) * FINx + f0 + tx];
        t[ty + 8*i][tx] = v;
        __nv_bfloat16 h, l;
        split_bf16(v, h, l);
        const size_t ridx = ((size_t)b * NN + n0 + ty + 8*i) * FINx + f0 + tx;
        fRhi[ridx] = h;
        fRlo[ridx] = l;
    }
    __syncthreads();
    #pragma unroll
    for (int i = 0; i < 4; i++) {
        const float v = t[tx][ty + 8*i];
        __nv_bfloat16 h, l;
        split_bf16(v, h, l);
        const size_t idx = ((size_t)b * FINx + f0 + ty + 8*i) * NN + n0 + tx;
        Fhi[idx] = h;
        Flo[idx] = l;
    }
}

// --------- Ax = h@a1, Ay = h@a2, e1[e] = feat row . L_w[e] (warp/row) -------
__global__ void small1_k(const __nv_bfloat16* __restrict__ hhi,
                         const __nv_bfloat16* __restrict__ hlo,
                         const float* __restrict__ feat,
                         const float* __restrict__ a1, const float* __restrict__ a2,
                         const float* __restrict__ Lw,
                         float* __restrict__ Ax, float* __restrict__ Ay,
                         float* __restrict__ e1)
{
    const int warp = (blockIdx.x * blockDim.x + threadIdx.x) >> 5;
    const int lane = threadIdx.x & 31;
    if (warp >= MTOT) return;

    const uint4 uh = *(const uint4*)(hhi + (size_t)warp * 512 + lane * 8);
    const uint4 ul = *(const uint4*)(hlo + (size_t)warp * 512 + lane * 8);
    const __nv_bfloat162* hp = (const __nv_bfloat162*)&uh;
    const __nv_bfloat162* lp = (const __nv_bfloat162*)&ul;
    float hv[8];
    #pragma unroll
    for (int i = 0; i < 4; i++) {
        const float2 a = __bfloat1622float2(hp[i]);
        const float2 bb = __bfloat1622float2(lp[i]);
        hv[2*i]   = a.x + bb.x;
        hv[2*i+1] = a.y + bb.y;
    }
    const float4* a14 = (const float4*)a1;
    const float4* a24 = (const float4*)a2;
    const float4 u0 = a14[lane*2], u1 = a14[lane*2+1];
    const float4 w0 = a24[lane*2], w1 = a24[lane*2+1];
    float sx = hv[0]*u0.x + hv[1]*u0.y + hv[2]*u0.z + hv[3]*u0.w
             + hv[4]*u1.x + hv[5]*u1.y + hv[6]*u1.z + hv[7]*u1.w;
    float sy = hv[0]*w0.x + hv[1]*w0.y + hv[2]*w0.z + hv[3]*w0.w
             + hv[4]*w1.x + hv[5]*w1.y + hv[6]*w1.z + hv[7]*w1.w;

    const float4* fr  = (const float4*)(feat + (size_t)warp * FINx);
    const float4* Lw4 = (const float4*)Lw;
    float acc[5] = {0.f, 0.f, 0.f, 0.f, 0.f};
    #pragma unroll
    for (int c = 0; c < 4; c++) {
        const float4 f = fr[lane + c * 32];
        #pragma unroll
        for (int e = 0; e < 5; e++) {
            const float4 w = Lw4[e * 128 + lane + c * 32];
            acc[e] += f.x*w.x + f.y*w.y + f.z*w.z + f.w*w.w;
        }
    }
    #pragma unroll
    for (int off = 16; off; off >>= 1) {
        sx += __shfl_xor_sync(0xffffffffu, sx, off);
        sy += __shfl_xor_sync(0xffffffffu, sy, off);
        #pragma unroll
        for (int e = 0; e < 5; e++) acc[e] += __shfl_xor_sync(0xffffffffu, acc[e], off);
    }
    if (lane == 0) {
        Ax[warp] = sx;
        Ay[warp] = sy;
        #pragma unroll
        for (int e = 0; e < 5; e++) e1[warp * 8 + e] = acc[e];
    }
}

// --------- e2[e] = fa row . R_w[e]; fa from fahi+falo -----------------------
__global__ void small2_k(const __nv_bfloat16* __restrict__ fhi,
                         const __nv_bfloat16* __restrict__ flo,
                         const float* __restrict__ Rw, float* __restrict__ e2)
{
    const int warp = (blockIdx.x * blockDim.x + threadIdx.x) >> 5;
    const int lane = threadIdx.x & 31;
    if (warp >= MTOT) return;

    const uint4* fh = (const uint4*)(fhi + (size_t)warp * FINx);
    const uint4* fl = (const uint4*)(flo + (size_t)warp * FINx);
    const float4* Rw4 = (const float4*)Rw;
    float acc[5] = {0.f, 0.f, 0.f, 0.f, 0.f};
    #pragma unroll
    for (int c = 0; c < 2; c++) {
        const uint4 uh = fh[lane + c * 32];
        const uint4 ul = fl[lane + c * 32];
        const __nv_bfloat162* hp = (const __nv_bfloat162*)&uh;
        const __nv_bfloat162* lp = (const __nv_bfloat162*)&ul;
        float v[8];
        #pragma unroll
        for (int i = 0; i < 4; i++) {
            const float2 a = __bfloat1622float2(hp[i]);
            const float2 bb = __bfloat1622float2(lp[i]);
            v[2*i]   = a.x + bb.x;
            v[2*i+1] = a.y + bb.y;
        }
        const int f4 = (lane + c * 32) * 2;
        #pragma unroll
        for (int e = 0; e < 5; e++) {
            const float4 w0 = Rw4[e * 128 + f4];
            const float4 w1 = Rw4[e * 128 + f4 + 1];
            acc[e] += v[0]*w0.x + v[1]*w0.y + v[2]*w0.z + v[3]*w0.w
                    + v[4]*w1.x + v[5]*w1.y + v[6]*w1.z + v[7]*w1.w;
        }
    }
    #pragma unroll
    for (int off = 16; off; off >>= 1) {
        #pragma unroll
        for (int e = 0; e < 5; e++) acc[e] += __shfl_xor_sync(0xffffffffu, acc[e], off);
    }
    if (lane == 0) {
        #pragma unroll
        for (int e = 0; e < 5; e++) e2[warp * 8 + e] = acc[e];
    }
}

// --------- out = h1 + h2 + e1^T B_w[o] e2  (h1 from hh1hi/lo) ---------------
__global__ void __launch_bounds__(256)
final_k(const __nv_bfloat16* __restrict__ hh1hi, const __nv_bfloat16* __restrict__ hh1lo,
        const float* __restrict__ h2,
        const float* __restrict__ e1, const float* __restrict__ e2,
        const float* __restrict__ Bw, float* __restrict__ out)
{
    const int m = blockIdx.x;
    const int o = threadIdx.x;   // 0..255
    __shared__ float s1[8], s2[8];
    if (o < 5) { s1[o] = e1[m * 8 + o]; s2[o] = e2[m * 8 + o]; }
    __syncthreads();

    const float* bw = Bw + o * 25;
    float s = 0.f;
    #pragma unroll
    for (int i = 0; i < 5; i++) {
        const float ei = s1[i];
        #pragma unroll
        for (int j = 0; j < 5; j++) s += ei * bw[i * 5 + j] * s2[j];
    }
    const size_t hidx = (size_t)m * 512 + 256 + o;
    const float h1v = __bfloat162float(hh1hi[hidx]) + __bfloat162float(hh1lo[hidx]);
    out[(size_t)m * FOUTx + o] = h1v + h2[(size_t)m * FOUTx + o] + s;
}

// ---------------------------------------------------------------------------
extern "C" void kernel_launch(void* const* d_in, const int* in_sizes, int n_in,
                              void* d_out, int out_size)
{
    const float* feat = (const float*)d_in[0];
    const int*   adj  = (const int*)  d_in[1];
    const float* W    = (const float*)d_in[2];
    const float* W1   = (const float*)d_in[3];
    const float* W2   = (const float*)d_in[4];
    const float* a1   = (const float*)d_in[5];
    const float* a2   = (const float*)d_in[6];
    const float* a12  = (const float*)d_in[7];
    const float* Lw   = (const float*)d_in[8];
    const float* Rw   = (const float*)d_in[9];
    const float* Bw   = (const float*)d_in[10];
    float* out = (float*)d_out;

    float *h2, *Ax, *Ay, *e1, *e2, *rowpart, *invsum;
    __nv_bfloat16 *hh1hi, *hh1lo, *Shi, *Slo, *Fhi, *Flo, *ghi, *glo;
    __nv_bfloat16 *fRhi, *fRlo, *fahi, *falo;
    __nv_bfloat16 *WW1th, *WW1tl, *W2th, *W2tl, *a12th, *a12tl;
    cudaGetSymbolAddress((void**)&hh1hi, g_hh1hi);
    cudaGetSymbolAddress((void**)&hh1lo, g_hh1lo);
    cudaGetSymbolAddress((void**)&h2, g_h2);
    cudaGetSymbolAddress((void**)&Ax, g_Ax);
    cudaGetSymbolAddress((void**)&Ay, g_Ay);
    cudaGetSymbolAddress((void**)&e1, g_e1);
    cudaGetSymbolAddress((void**)&e2, g_e2);
    cudaGetSymbolAddress((void**)&rowpart, g_rowpart);
    cudaGetSymbolAddress((void**)&invsum, g_invsum);
    cudaGetSymbolAddress((void**)&Shi, g_Shi);
    cudaGetSymbolAddress((void**)&Slo, g_Slo);
    cudaGetSymbolAddress((void**)&Fhi, g_Fhi);
    cudaGetSymbolAddress((void**)&Flo, g_Flo);
    cudaGetSymbolAddress((void**)&ghi, g_ghi);
    cudaGetSymbolAddress((void**)&glo, g_glo);
    cudaGetSymbolAddress((void**)&fRhi, g_fRhi);
    cudaGetSymbolAddress((void**)&fRlo, g_fRlo);
    cudaGetSymbolAddress((void**)&fahi, g_fahi);
    cudaGetSymbolAddress((void**)&falo, g_falo);
    cudaGetSymbolAddress((void**)&WW1th, g_WW1th);
    cudaGetSymbolAddress((void**)&WW1tl, g_WW1tl);
    cudaGetSymbolAddress((void**)&W2th, g_W2th);
    cudaGetSymbolAddress((void**)&W2tl, g_W2tl);
    cudaGetSymbolAddress((void**)&a12th, g_a12th);
    cudaGetSymbolAddress((void**)&a12tl, g_a12tl);

    static int smem_set = 0;
    if (!smem_set) {
        cudaFuncSetAttribute(mma_gemm_k<0>, cudaFuncAttributeMaxDynamicSharedMemorySize,
                             AGG_SMEM);
        cudaFuncSetAttribute(mma_gemm_k<3>, cudaFuncAttributeMaxDynamicSharedMemorySize,
                             AGG_SMEM);
        cudaFuncSetAttribute(mma_gemm_k<4>, cudaFuncAttributeMaxDynamicSharedMemorySize,
                             AGG_SMEM);
        cudaFuncSetAttribute(mma_gemm_k<5>, cudaFuncAttributeMaxDynamicSharedMemorySize,
                             AGG_SMEM);
        smem_set = 1;
    }

    const dim3 blk(256);
    const dim3 tb(32, 8);

    // weight transposes + splits (tiny); [W^T ; W1^T] fused
    tsplit_k<<<dim3(FOUTx/32, FINx/32), tb>>>(W,  WW1th,            WW1tl,            FINx, FOUTx);
    tsplit_k<<<dim3(FOUTx/32, FINx/32), tb>>>(W1, WW1th + 256*FINx, WW1tl + 256*FINx, FINx, FOUTx);
    tsplit_k<<<dim3(FOUTx/32, FINx/32), tb>>>(W2, W2th, W2tl, FINx, FOUTx);
    tsplit_k<<<dim3(FOUTx/32, FOUTx/32), tb>>>(a12, a12th, a12tl, FOUTx, FOUTx);

    // feat: transposed split + row-major split in one kernel
    transpose_split_k<<<dim3(NN/32, FINx/32, Bn), tb>>>(feat, Fhi, Flo, fRhi, fRlo);

    // [h | h1] = feat @ [W | W1]  (hi/lo only)
    mma_gemm_k<3><<<dim3(512/128, MTOT/128, 1), blk, AGG_SMEM>>>(
        fRhi, fRlo, WW1th, WW1tl, nullptr, FINx, FINx, FINx, MTOT, 512, 512,
        nullptr, nullptr, nullptr, nullptr, hh1hi, hh1lo);

    // Ax, Ay, e1
    small1_k<<<MTOT/8, 256>>>(hh1hi, hh1lo, feat, a1, a2, Lw, Ax, Ay, e1);

    // g = h @ a12  (hi/lo only)
    mma_gemm_k<3><<<dim3(FOUTx/128, MTOT/128, 1), blk, AGG_SMEM>>>(
        hh1hi, hh1lo, a12th, a12tl, nullptr, FOUTx, 512, FOUTx, MTOT, FOUTx, FOUTx,
        nullptr, nullptr, nullptr, nullptr, ghi, glo);

    // scores -> unnormalized probs (exp fused, row partial sums; no fp32 S)
    mma_gemm_k<5><<<dim3(NN/128, NN/128, Bn), blk, AGG_SMEM>>>(
        ghi, glo, hh1hi, hh1lo, nullptr, FOUTx, FOUTx, 512, NN, NN, NN,
        Ax, Ay, adj, rowpart, Shi, Slo);

    // invsum[row] = 1 / sum(rowpart)
    rowsum_inv_k<<<MTOT/8, 256>>>(rowpart, invsum);

    // feat_agg = (P_unnorm @ feat) * invsum  (normalized hi/lo out)
    mma_gemm_k<4><<<dim3(FINx/128, NN/128, Bn), blk, AGG_SMEM>>>(
        Shi, Slo, Fhi, Flo, nullptr, NN, NN, NN, NN, FINx, FINx,
        invsum, nullptr, nullptr, nullptr, fahi, falo);

    // h2 = fa @ W2 ; e2
    mma_gemm_k<0><<<dim3(FOUTx/128, MTOT/128, 1), blk, AGG_SMEM>>>(
        fahi, falo, W2th, W2tl, h2, FINx, FINx, FINx, MTOT, FOUTx, FOUTx,
        nullptr, nullptr, nullptr, nullptr, nullptr, nullptr);
    small2_k<<<MTOT/8, 256>>>(fahi, falo, Rw, e2);

    // out = h1 + h2 + bilinear(e1, B_w, e2)
    final_k<<<MTOT, 256>>>(hh1hi, hh1lo, h2, e1, e2, Bw, out);
}